// round 8
// baseline (speedup 1.0000x reference)
#include <cuda_runtime.h>
#include <cuda_fp16.h>
#include <cstdint>

#define Bsz 16384
#define Cn  8
#define Dd  256
#define H0n 512
#define H1n 256

// ---------------- scratch (device statics) ----------------
__device__ __align__(16) __half g_xh  [Bsz][Dd];           // 8MB   x fp16
__device__ __align__(16) __half g_w0h [Cn][H0n][Dd];       // 2MB   w0 fp16
__device__ __align__(16) __half g_w1h [Cn][H1n][H0n];      // 2MB   w1 fp16
__device__ __align__(16) __half g_h0  [Cn][Bsz][512];      // 134MB h0 fp16

// ---------------- prep: x, w0, w1 convert + out init, one launch ----------------
__device__ __forceinline__ uint4 cvt8h(const float* s) {
    uint32_t h[4];
    #pragma unroll
    for (int i = 0; i < 4; i++) {
        __half h0 = __float2half_rn(s[2*i]), h1 = __float2half_rn(s[2*i+1]);
        h[i] = (uint32_t)__half_as_ushort(h0) | ((uint32_t)__half_as_ushort(h1) << 16);
    }
    return make_uint4(h[0], h[1], h[2], h[3]);
}

__global__ void prep_all(const float* __restrict__ x,
                         const float* __restrict__ W0, const float* __restrict__ W1,
                         const float* __restrict__ b2g, float* __restrict__ out) {
    int u = blockIdx.x * blockDim.x + threadIdx.x;   // 786432 total
    float buf[8];
    if (u < 524288) {                                 // x: 16384*256/8
        int k8 = u & 31, b = u >> 5;
        *(float4*)(buf)   = *(const float4*)(x + (size_t)b * Dd + k8 * 8);
        *(float4*)(buf+4) = *(const float4*)(x + (size_t)b * Dd + k8 * 8 + 4);
        *(uint4*)&g_xh[b][k8 * 8] = cvt8h(buf);
    } else if (u < 655360) {                          // w0: 8*512*256/8
        int v = u - 524288;
        int k8 = v & 31, n = (v >> 5) & 511, c = v >> 14;
        const float* src = W0 + ((size_t)c * H0n + n) * Dd + k8 * 8;
        *(float4*)(buf)   = *(const float4*)(src);
        *(float4*)(buf+4) = *(const float4*)(src + 4);
        *(uint4*)&g_w0h[c][n][k8 * 8] = cvt8h(buf);
    } else {                                          // w1: 8*256*512/8 + out init
        int v = u - 655360;
        int k8 = v & 63, n = (v >> 6) & 255, c = v >> 14;
        const float* src = W1 + ((size_t)c * H1n + n) * H0n + k8 * 8;
        *(float4*)(buf)   = *(const float4*)(src);
        *(float4*)(buf+4) = *(const float4*)(src + 4);
        *(uint4*)&g_w1h[c][n][k8 * 8] = cvt8h(buf);
        out[v] = b2g[v & 7];
    }
}

// ---------------- GEMM machinery ----------------
__device__ __forceinline__ uint32_t smem_u32(const void* p) {
    uint32_t a;
    asm("{ .reg .u64 t; cvta.to.shared.u64 t, %1; cvt.u32.u64 %0, t; }" : "=r"(a) : "l"(p));
    return a;
}
#define CP16(dst, src) asm volatile("cp.async.cg.shared.global [%0], [%1], 16;" :: "r"(dst), "l"(src))
#define CP_COMMIT()    asm volatile("cp.async.commit_group;" ::: "memory")
#define CP_WAIT1()     asm volatile("cp.async.wait_group 1;" ::: "memory")
#define LDSM4(r, a) \
    asm volatile("ldmatrix.sync.aligned.m8n8.x4.shared.b16 {%0,%1,%2,%3}, [%4];" \
        : "=r"((r)[0]), "=r"((r)[1]), "=r"((r)[2]), "=r"((r)[3]) : "r"(a))
#define MMA(d, a, b0, b1) \
    asm volatile("mma.sync.aligned.m16n8k16.row.col.f32.f16.f16.f32 " \
        "{%0,%1,%2,%3}, {%4,%5,%6,%7}, {%8,%9}, {%0,%1,%2,%3};" \
        : "+f"((d)[0]), "+f"((d)[1]), "+f"((d)[2]), "+f"((d)[3]) \
        : "r"((a)[0]), "r"((a)[1]), "r"((a)[2]), "r"((a)[3]), "r"(b0), "r"(b1))

// stage: A[128][64]f16 (16KB) + B[128][64]f16 (16KB) = 32KB, 3 stages
#define STAGE_BYTES 32768
#define AUX_OFF     98304
#define SMEM_TOTAL  102400

// warp tile 64x64: 4 A-ldsm, 4 B-ldsm, 32 MMA per k16
#define COMPUTE_K16(s16) do {                                                  \
    uint32_t afr[4][4], bfr[4][4];                                             \
    _Pragma("unroll")                                                          \
    for (int mt = 0; mt < 4; mt++) {                                           \
        int row = wm0 + mt * 16 + (lane & 7) + ((lane >> 3) & 1) * 8;          \
        int g   = (s16) * 2 + (lane >> 4);                                     \
        LDSM4(afr[mt], sA + row * 128 + ((g ^ (row & 7)) << 4));               \
    }                                                                          \
    _Pragma("unroll")                                                          \
    for (int ng = 0; ng < 4; ng++) {                                           \
        int row = wn0 + ng * 16 + (lane & 7) + ((lane >> 4) << 3);             \
        int g   = (s16) * 2 + ((lane >> 3) & 1);                               \
        LDSM4(bfr[ng], sB + row * 128 + ((g ^ (row & 7)) << 4));               \
    }                                                                          \
    _Pragma("unroll")                                                          \
    for (int mt = 0; mt < 4; mt++)                                             \
        _Pragma("unroll")                                                      \
        for (int ni = 0; ni < 8; ni++)                                         \
            MMA(acc[mt][ni], afr[mt], bfr[ni >> 1][(ni & 1) * 2],              \
                bfr[ni >> 1][(ni & 1) * 2 + 1]);                               \
} while (0)

#define ACC_ZERO()                                                             \
    float acc[4][8][4];                                                        \
    _Pragma("unroll")                                                          \
    for (int a = 0; a < 4; a++)                                                \
        _Pragma("unroll")                                                      \
        for (int b = 0; b < 8; b++)                                            \
            _Pragma("unroll")                                                  \
            for (int r = 0; r < 4; r++) acc[a][b][r] = 0.0f;

// ============ Kernel A: h0 = relu(x @ w0h^T + b0) -> g_h0 (fp16) ============
__global__ void __launch_bounds__(128, 2)
gemm0(const float* __restrict__ b0g)
{
    extern __shared__ __align__(128) uint8_t sm[];
    const uint32_t sb = smem_u32(sm);
    const int tid = threadIdx.x, lane = tid & 31, wid = tid >> 5;
    const int wm0 = (wid & 1) * 64, wn0 = (wid >> 1) * 64;
    const int m0 = blockIdx.x * 128, n0 = blockIdx.y * 128, c = blockIdx.z;
    const int prow = tid >> 3, pg = tid & 7;
    const uint32_t pdst = sb + prow * 128 + ((pg ^ (prow & 7)) << 4);

    float* b0s = (float*)(sm + AUX_OFF);
    if (tid < 128) b0s[tid] = b0g[c * H0n + n0 + tid];

#define PRODUCE_A0(s, t) do {                                                  \
    _Pragma("unroll")                                                          \
    for (int i = 0; i < 8; i++) {                                              \
        int row = prow + i * 16;                                               \
        uint32_t d = pdst + (s) * STAGE_BYTES + i * 2048;                      \
        CP16(d,         &g_xh[m0 + row][(t) * 64 + pg * 8]);                   \
        CP16(d + 16384, &g_w0h[c][n0 + row][(t) * 64 + pg * 8]);               \
    }                                                                          \
} while (0)

    PRODUCE_A0(0, 0); CP_COMMIT();
    PRODUCE_A0(1, 1); CP_COMMIT();

    ACC_ZERO();

    #pragma unroll 1
    for (int t = 0; t < 4; t++) {
        CP_WAIT1();
        __syncthreads();
        if (t + 2 < 4) { PRODUCE_A0((t + 2) % 3, t + 2); }
        CP_COMMIT();
        const uint32_t sA = sb + (t % 3) * STAGE_BYTES;
        const uint32_t sB = sA + 16384;
        #pragma unroll
        for (int s16 = 0; s16 < 4; s16++) COMPUTE_K16(s16);
    }

    // epilogue: relu(+b0) -> fp16 -> g_h0[c][m][n]
    #pragma unroll
    for (int mt = 0; mt < 4; mt++) {
        #pragma unroll
        for (int ni = 0; ni < 8; ni++) {
            const int nl = wn0 + ni * 8 + (lane & 3) * 2;
            const int n = n0 + nl;
            const float bn0 = b0s[nl], bn1 = b0s[nl + 1];
            #pragma unroll
            for (int half = 0; half < 2; half++) {
                const int m = m0 + wm0 + mt * 16 + (lane >> 2) + half * 8;
                float v0 = fmaxf(acc[mt][ni][half * 2 + 0] + bn0, 0.0f);
                float v1 = fmaxf(acc[mt][ni][half * 2 + 1] + bn1, 0.0f);
                __half h0 = __float2half_rn(v0), h1 = __float2half_rn(v1);
                uint32_t hp = (uint32_t)__half_as_ushort(h0) | ((uint32_t)__half_as_ushort(h1) << 16);
                *(uint32_t*)&g_h0[c][m][n] = hp;
            }
        }
    }
}

// ============ Kernel B: out += relu(h0 @ w1h^T + b1) . w2 (partial per n-tile) ============
__global__ void __launch_bounds__(128, 2)
gemm1(const float* __restrict__ b1g, const float* __restrict__ w2g,
      float* __restrict__ out)
{
    extern __shared__ __align__(128) uint8_t sm[];
    const uint32_t sb = smem_u32(sm);
    const int tid = threadIdx.x, lane = tid & 31, wid = tid >> 5;
    const int wm0 = (wid & 1) * 64, wn0 = (wid >> 1) * 64;
    const int m0 = blockIdx.x * 128, n0 = blockIdx.y * 128, c = blockIdx.z;
    const int prow = tid >> 3, pg = tid & 7;
    const uint32_t pdst = sb + prow * 128 + ((pg ^ (prow & 7)) << 4);

    float* b1s = (float*)(sm + AUX_OFF);
    float* w2s = (float*)(sm + AUX_OFF + 512);
    float* red = (float*)(sm + AUX_OFF + 1024);     // [128][2]
    if (tid < 128) {
        b1s[tid] = b1g[c * H1n + n0 + tid];
        w2s[tid] = w2g[c * H1n + n0 + tid];
    }

#define PRODUCE_A1(s, t) do {                                                  \
    _Pragma("unroll")                                                          \
    for (int i = 0; i < 8; i++) {                                              \
        int row = prow + i * 16;                                               \
        uint32_t d = pdst + (s) * STAGE_BYTES + i * 2048;                      \
        CP16(d,         &g_h0[c][m0 + row][(t) * 64 + pg * 8]);                \
        CP16(d + 16384, &g_w1h[c][n0 + row][((t) & 7) * 64 + pg * 8]);         \
    }                                                                          \
} while (0)

    PRODUCE_A1(0, 0); CP_COMMIT();
    PRODUCE_A1(1, 1); CP_COMMIT();

    ACC_ZERO();

    #pragma unroll 1
    for (int t = 0; t < 8; t++) {
        CP_WAIT1();
        __syncthreads();
        if (t + 2 < 8) { PRODUCE_A1((t + 2) % 3, t + 2); }
        CP_COMMIT();
        const uint32_t sA = sb + (t % 3) * STAGE_BYTES;
        const uint32_t sB = sA + 16384;
        #pragma unroll
        for (int s16 = 0; s16 < 4; s16++) COMPUTE_K16(s16);
    }

    // epilogue: relu(+b1) . w2 partial dot over this CTA's 128 n's
    float s[8];
    #pragma unroll
    for (int i = 0; i < 8; i++) s[i] = 0.0f;
    #pragma unroll
    for (int mt = 0; mt < 4; mt++) {
        #pragma unroll
        for (int ni = 0; ni < 8; ni++) {
            const int nl = wn0 + ni * 8 + (lane & 3) * 2;
            const float bn0 = b1s[nl], bn1 = b1s[nl + 1];
            const float w0v = w2s[nl], w1v = w2s[nl + 1];
            s[mt * 2 + 0] += fmaxf(acc[mt][ni][0] + bn0, 0.0f) * w0v
                           + fmaxf(acc[mt][ni][1] + bn1, 0.0f) * w1v;
            s[mt * 2 + 1] += fmaxf(acc[mt][ni][2] + bn0, 0.0f) * w0v
                           + fmaxf(acc[mt][ni][3] + bn1, 0.0f) * w1v;
        }
    }
    #pragma unroll
    for (int i = 0; i < 8; i++) {
        s[i] += __shfl_xor_sync(0xFFFFFFFF, s[i], 1);
        s[i] += __shfl_xor_sync(0xFFFFFFFF, s[i], 2);
    }
    __syncthreads();
    if ((lane & 3) == 0) {
        #pragma unroll
        for (int mt = 0; mt < 4; mt++)
            #pragma unroll
            for (int half = 0; half < 2; half++) {
                int r = wm0 + mt * 16 + half * 8 + (lane >> 2);
                red[r * 2 + (wid >> 1)] = s[mt * 2 + half];
            }
    }
    __syncthreads();
    if (tid < 128) {
        float v = red[tid * 2] + red[tid * 2 + 1];
        atomicAdd(&out[(size_t)(m0 + tid) * Cn + c], v);
    }
}

extern "C" void kernel_launch(void* const* d_in, const int* in_sizes, int n_in,
                              void* d_out, int out_size) {
    (void)in_sizes; (void)n_in; (void)out_size;
    const float* x  = (const float*)d_in[0];
    const float* W0 = (const float*)d_in[1];
    const float* b0 = (const float*)d_in[2];
    const float* W1 = (const float*)d_in[3];
    const float* b1 = (const float*)d_in[4];
    const float* W2 = (const float*)d_in[5];
    const float* b2 = (const float*)d_in[6];
    float* out = (float*)d_out;

    prep_all<<<3072, 256>>>(x, W0, W1, b2, out);

    cudaFuncSetAttribute(gemm0, cudaFuncAttributeMaxDynamicSharedMemorySize, SMEM_TOTAL);
    cudaFuncSetAttribute(gemm1, cudaFuncAttributeMaxDynamicSharedMemorySize, SMEM_TOTAL);

    gemm0<<<dim3(128, 4, 8), 128, SMEM_TOTAL>>>(b0);
    gemm1<<<dim3(128, 2, 8), 128, SMEM_TOTAL>>>(b1, W2, out);
}

// round 9
// speedup vs baseline: 1.0656x; 1.0656x over previous
#include <cuda_runtime.h>
#include <cuda_fp16.h>
#include <cstdint>

#define Bsz 16384
#define Cn  8
#define Dd  256
#define H0n 512
#define H1n 256

// ---------------- scratch (device statics) ----------------
__device__ __align__(16) __half g_xh  [Bsz][Dd];           // 8MB   x fp16
__device__ __align__(16) __half g_w0h [Cn][H0n][Dd];       // 2MB   w0 fp16
__device__ __align__(16) __half g_w1h [Cn][H1n][H0n];      // 2MB   w1 fp16

// ---------------- prep: x, w0, w1 convert, one launch ----------------
__device__ __forceinline__ uint4 cvt8h(const float* s) {
    uint32_t h[4];
    #pragma unroll
    for (int i = 0; i < 4; i++) {
        __half h0 = __float2half_rn(s[2*i]), h1 = __float2half_rn(s[2*i+1]);
        h[i] = (uint32_t)__half_as_ushort(h0) | ((uint32_t)__half_as_ushort(h1) << 16);
    }
    return make_uint4(h[0], h[1], h[2], h[3]);
}

__global__ void prep_all(const float* __restrict__ x,
                         const float* __restrict__ W0, const float* __restrict__ W1) {
    int u = blockIdx.x * blockDim.x + threadIdx.x;   // 786432 total
    float buf[8];
    if (u < 524288) {                                 // x: 16384*256/8
        int k8 = u & 31, b = u >> 5;
        *(float4*)(buf)   = *(const float4*)(x + (size_t)b * Dd + k8 * 8);
        *(float4*)(buf+4) = *(const float4*)(x + (size_t)b * Dd + k8 * 8 + 4);
        *(uint4*)&g_xh[b][k8 * 8] = cvt8h(buf);
    } else if (u < 655360) {                          // w0: 8*512*256/8
        int v = u - 524288;
        int k8 = v & 31, n = (v >> 5) & 511, c = v >> 14;
        const float* src = W0 + ((size_t)c * H0n + n) * Dd + k8 * 8;
        *(float4*)(buf)   = *(const float4*)(src);
        *(float4*)(buf+4) = *(const float4*)(src + 4);
        *(uint4*)&g_w0h[c][n][k8 * 8] = cvt8h(buf);
    } else {                                          // w1: 8*256*512/8
        int v = u - 655360;
        int k8 = v & 63, n = (v >> 6) & 255, c = v >> 14;
        const float* src = W1 + ((size_t)c * H1n + n) * H0n + k8 * 8;
        *(float4*)(buf)   = *(const float4*)(src);
        *(float4*)(buf+4) = *(const float4*)(src + 4);
        *(uint4*)&g_w1h[c][n][k8 * 8] = cvt8h(buf);
    }
}

// ---------------- machinery ----------------
__device__ __forceinline__ uint32_t smem_u32(const void* p) {
    uint32_t a;
    asm("{ .reg .u64 t; cvta.to.shared.u64 t, %1; cvt.u32.u64 %0, t; }" : "=r"(a) : "l"(p));
    return a;
}
#define CP16(dst, src) asm volatile("cp.async.cg.shared.global [%0], [%1], 16;" :: "r"(dst), "l"(src))
#define CP_COMMIT()    asm volatile("cp.async.commit_group;" ::: "memory")
#define CP_WAIT0()     asm volatile("cp.async.wait_group 0;" ::: "memory")
#define LDSM4(r, a) \
    asm volatile("ldmatrix.sync.aligned.m8n8.x4.shared.b16 {%0,%1,%2,%3}, [%4];" \
        : "=r"((r)[0]), "=r"((r)[1]), "=r"((r)[2]), "=r"((r)[3]) : "r"(a))
#define MMA(d, a, b0, b1) \
    asm volatile("mma.sync.aligned.m16n8k16.row.col.f32.f16.f16.f32 " \
        "{%0,%1,%2,%3}, {%4,%5,%6,%7}, {%8,%9}, {%0,%1,%2,%3};" \
        : "+f"((d)[0]), "+f"((d)[1]), "+f"((d)[2]), "+f"((d)[3]) \
        : "r"((a)[0]), "r"((a)[1]), "r"((a)[2]), "r"((a)[3]), "r"(b0), "r"(b1))

// ---- smem layout (bytes) ----
// h0 tile:  [0, 131072)              128 rows x 1024B (512 fp16), XOR-swizzled rows
// ring:     [131072, 229376)         2 stages x 48KB; stage: A 16KB @ +0, B 32KB @ +16384
// red:      reuses ring stage0 A-slot (L1 never touches A-slots)
#define H0S   0
#define RING  131072
#define STG   49152
#define SMEM_TOTAL 229376

// B-fragment loads from ring stage (rows of 128B, swizzled)
#define LOADB(sB) do {                                                         \
    _Pragma("unroll")                                                          \
    for (int ng = 0; ng < 4; ng++) {                                           \
        int row = wn0 + ng * 16 + (lane & 7) + ((lane >> 4) << 3);             \
        int g   = s16 * 2 + ((lane >> 3) & 1);                                 \
        LDSM4(bfr[ng], (sB) + row * 128 + ((g ^ (row & 7)) << 4));             \
    }                                                                          \
} while (0)

#define DOMMA() \
    _Pragma("unroll")                                                          \
    for (int mt = 0; mt < 4; mt++)                                             \
        _Pragma("unroll")                                                      \
        for (int ni = 0; ni < 8; ni++)                                         \
            MMA(acc[mt][ni], afr[mt], bfr[ni >> 1][(ni & 1) * 2],              \
                bfr[ni >> 1][(ni & 1) * 2 + 1])

// ============ fused: h0 = relu(x@w0^T+b0) in smem; out = relu(h0@w1^T+b1).w2 + b2 ============
__global__ void __launch_bounds__(256, 1)
fused(const float* __restrict__ b0g, const float* __restrict__ b1g,
      const float* __restrict__ w2g, const float* __restrict__ b2g,
      float* __restrict__ out)
{
    extern __shared__ __align__(128) uint8_t sm[];
    const uint32_t sb = smem_u32(sm);
    const int tid = threadIdx.x, lane = tid & 31, wid = tid >> 5;
    const int wm0 = (wid & 1) * 64, wn0 = (wid >> 1) * 64;
    const int m0 = blockIdx.x * 128, c = blockIdx.y;
    const int prow = tid >> 3, pg = tid & 7;   // prow 0..31
    const uint32_t pdst = sb + RING + prow * 128 + ((pg ^ (prow & 7)) << 4);

// L0 produce: step = 0..7 (nchunk = step>>2, t = step&3), stage s = A 16KB + B 32KB
#define PRODUCE_L0(s, step) do {                                               \
    const int _t = (step) & 3, _nc = (step) >> 2;                              \
    _Pragma("unroll")                                                          \
    for (int i = 0; i < 4; i++) {                                              \
        int row = prow + i * 32;                                               \
        CP16(pdst + (s) * STG + i * 4096,                                      \
             &g_xh[m0 + row][_t * 64 + pg * 8]);                               \
    }                                                                          \
    _Pragma("unroll")                                                          \
    for (int i = 0; i < 8; i++) {                                              \
        int row = prow + i * 32;                                               \
        CP16(pdst + (s) * STG + 16384 + i * 4096,                              \
             &g_w0h[c][_nc * 256 + row][_t * 64 + pg * 8]);                    \
    }                                                                          \
} while (0)

// L1 produce: B only (w1), step u = 0..7
#define PRODUCE_L1(s, u) do {                                                  \
    _Pragma("unroll")                                                          \
    for (int i = 0; i < 8; i++) {                                              \
        int row = prow + i * 32;                                               \
        CP16(pdst + (s) * STG + 16384 + i * 4096,                              \
             &g_w1h[c][row][(u) * 64 + pg * 8]);                               \
    }                                                                          \
} while (0)

    float acc[4][8][4];
    #pragma unroll
    for (int a = 0; a < 4; a++)
        #pragma unroll
        for (int b = 0; b < 8; b++)
            #pragma unroll
            for (int r = 0; r < 4; r++) acc[a][b][r] = 0.0f;

    // =================== Layer 0 ===================
    PRODUCE_L0(0, 0); CP_COMMIT();

    #pragma unroll 1
    for (int s = 0; s < 8; s++) {
        CP_WAIT0();
        __syncthreads();
        if (s < 7) { PRODUCE_L0((s + 1) & 1, s + 1); }
        CP_COMMIT();
        const uint32_t sA = sb + RING + (s & 1) * STG;
        const uint32_t sB = sA + 16384;
        #pragma unroll
        for (int s16 = 0; s16 < 4; s16++) {
            uint32_t afr[4][4], bfr[4][4];
            #pragma unroll
            for (int mt = 0; mt < 4; mt++) {
                int row = wm0 + mt * 16 + (lane & 7) + ((lane >> 3) & 1) * 8;
                int g   = s16 * 2 + (lane >> 4);
                LDSM4(afr[mt], sA + row * 128 + ((g ^ (row & 7)) << 4));
            }
            LOADB(sB);
            DOMMA();
        }

        if ((s & 3) == 3) {
            // epilogue for n-chunk (s>>2): relu(+b0) -> fp16 -> smem h0 tile
            const int nc = s >> 2;
            #pragma unroll
            for (int mt = 0; mt < 4; mt++) {
                #pragma unroll
                for (int ni = 0; ni < 8; ni++) {
                    const int n = nc * 256 + wn0 + ni * 8 + (lane & 3) * 2;
                    const float bn0 = b0g[c * H0n + n];
                    const float bn1 = b0g[c * H0n + n + 1];
                    #pragma unroll
                    for (int half = 0; half < 2; half++) {
                        const int m = wm0 + mt * 16 + (lane >> 2) + half * 8;
                        float v0 = fmaxf(acc[mt][ni][half * 2 + 0] + bn0, 0.0f);
                        float v1 = fmaxf(acc[mt][ni][half * 2 + 1] + bn1, 0.0f);
                        __half h0 = __float2half_rn(v0), h1 = __float2half_rn(v1);
                        uint32_t hp = (uint32_t)__half_as_ushort(h0)
                                    | ((uint32_t)__half_as_ushort(h1) << 16);
                        *(uint32_t*)(sm + H0S + m * 1024 + ((2 * n) ^ ((m & 7) << 4))) = hp;
                    }
                }
            }
            #pragma unroll
            for (int a = 0; a < 4; a++)
                #pragma unroll
                for (int b = 0; b < 8; b++)
                    #pragma unroll
                    for (int r = 0; r < 4; r++) acc[a][b][r] = 0.0f;
        }
    }

    __syncthreads();    // h0 tile complete & visible; ring fully free

    // =================== Layer 1 ===================
    PRODUCE_L1(0, 0); CP_COMMIT();

    #pragma unroll 1
    for (int u = 0; u < 8; u++) {
        CP_WAIT0();
        __syncthreads();
        if (u < 7) { PRODUCE_L1((u + 1) & 1, u + 1); }
        CP_COMMIT();
        const uint32_t sB = sb + RING + (u & 1) * STG + 16384;
        #pragma unroll
        for (int s16 = 0; s16 < 4; s16++) {
            uint32_t afr[4][4], bfr[4][4];
            #pragma unroll
            for (int mt = 0; mt < 4; mt++) {
                int row = wm0 + mt * 16 + (lane & 7) + ((lane >> 3) & 1) * 8;
                int g   = u * 8 + s16 * 2 + (lane >> 4);      // k16-group 0..63
                LDSM4(afr[mt], sb + H0S + row * 1024 + (((uint32_t)g << 4) ^ ((row & 7) << 4)));
            }
            LOADB(sB);
            DOMMA();
        }
    }

    // =================== final epilogue: relu(+b1).w2 + b2 ===================
    float s[8];
    #pragma unroll
    for (int i = 0; i < 8; i++) s[i] = 0.0f;
    #pragma unroll
    for (int mt = 0; mt < 4; mt++) {
        #pragma unroll
        for (int ni = 0; ni < 8; ni++) {
            const int n = wn0 + ni * 8 + (lane & 3) * 2;
            const float bn0 = b1g[c * H1n + n],  bn1 = b1g[c * H1n + n + 1];
            const float w0v = w2g[c * H1n + n],  w1v = w2g[c * H1n + n + 1];
            s[mt * 2 + 0] += fmaxf(acc[mt][ni][0] + bn0, 0.0f) * w0v
                           + fmaxf(acc[mt][ni][1] + bn1, 0.0f) * w1v;
            s[mt * 2 + 1] += fmaxf(acc[mt][ni][2] + bn0, 0.0f) * w0v
                           + fmaxf(acc[mt][ni][3] + bn1, 0.0f) * w1v;
        }
    }
    #pragma unroll
    for (int i = 0; i < 8; i++) {
        s[i] += __shfl_xor_sync(0xFFFFFFFF, s[i], 1);
        s[i] += __shfl_xor_sync(0xFFFFFFFF, s[i], 2);
    }
    float* red = (float*)(sm + RING);   // reuse dead ring A-slot: [128][4]
    __syncthreads();
    if ((lane & 3) == 0) {
        #pragma unroll
        for (int mt = 0; mt < 4; mt++)
            #pragma unroll
            for (int half = 0; half < 2; half++) {
                int r = wm0 + mt * 16 + half * 8 + (lane >> 2);
                red[r * 4 + (wid >> 1)] = s[mt * 2 + half];
            }
    }
    __syncthreads();
    if (tid < 128) {
        float v = red[tid * 4] + red[tid * 4 + 1] + red[tid * 4 + 2] + red[tid * 4 + 3];
        out[(size_t)(m0 + tid) * Cn + c] = v + b2g[c];
    }
}

extern "C" void kernel_launch(void* const* d_in, const int* in_sizes, int n_in,
                              void* d_out, int out_size) {
    (void)in_sizes; (void)n_in; (void)out_size;
    const float* x  = (const float*)d_in[0];
    const float* W0 = (const float*)d_in[1];
    const float* b0 = (const float*)d_in[2];
    const float* W1 = (const float*)d_in[3];
    const float* b1 = (const float*)d_in[4];
    const float* W2 = (const float*)d_in[5];
    const float* b2 = (const float*)d_in[6];
    float* out = (float*)d_out;

    prep_all<<<3072, 256>>>(x, W0, W1);

    cudaFuncSetAttribute(fused, cudaFuncAttributeMaxDynamicSharedMemorySize, SMEM_TOTAL);
    fused<<<dim3(128, 8), 256, SMEM_TOTAL>>>(b0, b1, W2, b2, out);
}